// round 6
// baseline (speedup 1.0000x reference)
#include <cuda_runtime.h>
#include <cuda_fp16.h>
#include <cstdint>
#include <cstddef>

// ---------------- problem constants ----------------
#define EXPERTS 8
#define HDIM    2048
#define FDIM    8192
#define TOKENS  16384
#define CAP     2048

// fp16 staging buffers (static __device__ memory: allocation-guard safe)
__device__ __half g_xh [(size_t)TOKENS  * HDIM];          //  64 MB
__device__ __half g_w1h[(size_t)EXPERTS * HDIM * FDIM];   // 256 MB
__device__ __half g_w2h[(size_t)EXPERTS * FDIM * HDIM];   // 256 MB
__device__ __half g_hidh[(size_t)TOKENS * FDIM];          // 256 MB

// ---------------- fp32 -> fp16 (RN) bulk convert ----------------
__global__ void cvt_f2h(const float* __restrict__ s, __half* __restrict__ d, size_t n4) {
    size_t i      = blockIdx.x * (size_t)blockDim.x + threadIdx.x;
    size_t stride = (size_t)gridDim.x * blockDim.x;
    const float4* s4 = (const float4*)s;
    __half2*      d2 = (__half2*)d;
    for (; i < n4; i += stride) {
        float4 v = s4[i];
        d2[2 * i]     = __floats2half2_rn(v.x, v.y);
        d2[2 * i + 1] = __floats2half2_rn(v.z, v.w);
    }
}

// ---------------- PTX helpers ----------------
__device__ __forceinline__ uint32_t smem_u32(const void* p) {
    uint32_t a;
    asm("{ .reg .u64 t; cvta.to.shared.u64 t, %1; cvt.u32.u64 %0, t; }" : "=r"(a) : "l"(p));
    return a;
}
__device__ __forceinline__ void cpa16(uint32_t dst, const void* src) {
    asm volatile("cp.async.cg.shared.global [%0], [%1], 16;" :: "r"(dst), "l"(src));
}
#define CP_COMMIT() asm volatile("cp.async.commit_group;" ::: "memory")
#define CP_WAIT1()  asm volatile("cp.async.wait_group 1;"  ::: "memory")

__device__ __forceinline__ void ldsm_x4(uint32_t* r, uint32_t a) {
    asm volatile("ldmatrix.sync.aligned.m8n8.x4.shared.b16 {%0,%1,%2,%3}, [%4];"
                 : "=r"(r[0]), "=r"(r[1]), "=r"(r[2]), "=r"(r[3]) : "r"(a));
}
__device__ __forceinline__ void ldsm_x4t(uint32_t* r, uint32_t a) {
    asm volatile("ldmatrix.sync.aligned.m8n8.x4.trans.shared.b16 {%0,%1,%2,%3}, [%4];"
                 : "=r"(r[0]), "=r"(r[1]), "=r"(r[2]), "=r"(r[3]) : "r"(a));
}
__device__ __forceinline__ void mma16816(float* c, const uint32_t* a, const uint32_t* b) {
    asm volatile(
        "mma.sync.aligned.m16n8k16.row.col.f32.f16.f16.f32 "
        "{%0,%1,%2,%3}, {%4,%5,%6,%7}, {%8,%9}, {%0,%1,%2,%3};"
        : "+f"(c[0]), "+f"(c[1]), "+f"(c[2]), "+f"(c[3])
        : "r"(a[0]), "r"(a[1]), "r"(a[2]), "r"(a[3]), "r"(b[0]), "r"(b[1]));
}

__device__ __forceinline__ float gelu_tanh(float x) {
    float x3 = x * x * x;
    float t  = tanhf(0.7978845608028654f * (x + 0.044715f * x3));
    return 0.5f * x * (1.0f + t);
}

// ---------------- SMEM layout ----------------
// BM=128, BN=128, BK=32, 4-stage ring (stage index = it & 3).
// A stage: 128 rows x 64B padded to 80B pitch  (5 x 16B, gcd(5,8)=1)  -> 10240 B
// B stage:  32 k-rows x 256B padded to 272B   (17 x 16B, gcd(17,8)=1) ->  8704 B
// 4 stages: 75776 B -> 2 CTAs/SM.
static constexpr int A_PITCH   = 80;
static constexpr int B_PITCH   = 272;
static constexpr int A_STAGE   = 128 * A_PITCH;         // 10240
static constexpr int B_STAGE   = 32 * B_PITCH;          //  8704
static constexpr int NSTAGE    = 4;
static constexpr int B_OFF     = NSTAGE * A_STAGE;      // 40960
static constexpr int SMEM_SIZE = B_OFF + NSTAGE * B_STAGE;  // 75776

// ---------------- grouped GEMM: OUT[e] = act(A[e] @ W[e] + bias[e]) ----------------
// Pipeline invariant: the barrier ending iteration `it` is preceded by
// cp.async.wait_group 1, so stages <= it+2 are complete and visible to all
// threads during iteration it+1. This lets us LDSM the A fragments of stage
// it+1 BEFORE the barrier (explicit double buffer) so MMAs resume instantly
// after it — removing the post-barrier LDSM bubble ptxas cannot hoist.
template <bool FC1>
__global__ void __launch_bounds__(256, 2)
moe_gemm(const float* __restrict__ bias, float* __restrict__ out, int K, int N)
{
    extern __shared__ char smem[];
    const uint32_t sb = smem_u32(smem);
    const int tid  = threadIdx.x;
    const int wid  = tid >> 5;
    const int lane = tid & 31;

    const int e  = blockIdx.z;
    const int m0 = blockIdx.y * 128;
    const int n0 = blockIdx.x * 128;

    const __half* A = (FC1 ? g_xh  : g_hidh) + ((size_t)(e * CAP + m0)) * (size_t)K;
    const __half* W = (FC1 ? g_w1h : g_w2h) + (size_t)e * K * N + n0;

    const int wm = (wid & 1) * 64;   // warp row offset
    const int wn = (wid >> 1) * 32;  // warp col offset

    // producer mapping: A tile 512 segs (4/row), B tile 512 segs (16/row); 2 each/thread
    auto load_stage = [&](int stage, int kc) {
        uint32_t aS = sb + stage * A_STAGE;
        uint32_t bS = sb + B_OFF + stage * B_STAGE;
        #pragma unroll
        for (int j = 0; j < 2; ++j) {
            const int idx = tid + 256 * j;
            const int row = idx >> 2, seg = idx & 3;
            cpa16(aS + row * A_PITCH + seg * 16,
                  A + (size_t)row * K + kc + seg * 8);
        }
        #pragma unroll
        for (int j = 0; j < 2; ++j) {
            const int idx = tid + 256 * j;
            const int r = idx >> 4, seg = idx & 15;
            cpa16(bS + r * B_PITCH + seg * 16,
                  W + (size_t)(kc + r) * N + seg * 8);
        }
    };

    const int nk = K / 32;
    load_stage(0, 0);  CP_COMMIT();
    load_stage(1, 32); CP_COMMIT();
    load_stage(2, 64); CP_COMMIT();

    float acc[4][4][4];
    #pragma unroll
    for (int i = 0; i < 4; ++i)
        #pragma unroll
        for (int j = 0; j < 4; ++j)
            #pragma unroll
            for (int q = 0; q < 4; ++q) acc[i][j][q] = 0.f;

    const int gid = lane >> 2, tig = lane & 3;
    // A ldmatrix (x4, non-trans)
    const uint32_t a_row  = lane & 15;
    const uint32_t a_koff = (lane >> 4) * 16;
    // B ldmatrix (x4, trans): mats 0,1 -> k 0-7/8-15; mats 2,3 -> +8 cols
    const int bmat  = lane >> 3;
    const int bt_k  = (bmat & 1) * 8 + (lane & 7);
    const int bt_n  = (bmat >> 1) * 8;

    // per-warp invariant pieces of LDSM addresses
    const uint32_t aOffBase = (wm + a_row) * A_PITCH + a_koff;   // + mt*16*A_PITCH + ks*32
    const uint32_t bOffBase = bt_k * B_PITCH + (wn + bt_n) * 2;  // + ks*16*B_PITCH + nh*32

    auto load_a_frags = [&](uint32_t (*a)[4], int stage, int ks) {
        const uint32_t base = sb + stage * A_STAGE + aOffBase + ks * 32;
        #pragma unroll
        for (int mt = 0; mt < 4; ++mt)
            ldsm_x4(a[mt], base + mt * (16 * A_PITCH));
    };

    // A-fragment double buffer (cross-barrier pipeline)
    uint32_t afrag[2][4][4];

    CP_WAIT1();            // stages 0,1 complete (stage 2 may be in flight)
    __syncthreads();       // visible to all threads
    load_a_frags(afrag[0], 0, 0);

    for (int it = 0; it < nk; ++it) {
        const int s = it & 3;
        const int pre = it + 3;
        if (pre < nk) { load_stage(pre & 3, pre * 32); CP_COMMIT(); }  // post-barrier: slot (it-1)&3 is free

        const uint32_t bS = sb + B_OFF + s * B_STAGE;

        // ---- k-step 0: A frags already resident (loaded before last barrier) ----
        {
            uint32_t b0[2][4];
            #pragma unroll
            for (int nh = 0; nh < 2; ++nh)
                ldsm_x4t(b0[nh], bS + bOffBase + nh * 32);
            load_a_frags(afrag[1], s, 1);            // prefetch ks1 A frags
            #pragma unroll
            for (int mt = 0; mt < 4; ++mt)
                #pragma unroll
                for (int nt = 0; nt < 4; ++nt)
                    mma16816(acc[mt][nt], afrag[0][mt], &b0[nt >> 1][(nt & 1) * 2]);
        }
        // ---- k-step 1: prefetch next stage's ks0 A frags BEFORE the barrier ----
        {
            uint32_t b1[2][4];
            #pragma unroll
            for (int nh = 0; nh < 2; ++nh)
                ldsm_x4t(b1[nh], bS + bOffBase + 16 * B_PITCH + nh * 32);
            if (it + 1 < nk)
                load_a_frags(afrag[0], (it + 1) & 3, 0);  // stage it+1 visible since barrier B_it
            #pragma unroll
            for (int mt = 0; mt < 4; ++mt)
                #pragma unroll
                for (int nt = 0; nt < 4; ++nt)
                    mma16816(acc[mt][nt], afrag[1][mt], &b1[nt >> 1][(nt & 1) * 2]);
        }

        if (it + 1 < nk) {
            CP_WAIT1();        // stages <= it+2 complete
            __syncthreads();   // B_{it+1}: visibility + stage-reuse guard
        }
    }

    // ---------------- epilogue ----------------
    const float* Bb = bias + (size_t)e * N + n0;
    #pragma unroll
    for (int mt = 0; mt < 4; ++mt) {
        const int r0 = wm + mt * 16 + gid;           // rows r0 and r0+8
        #pragma unroll
        for (int nt = 0; nt < 4; ++nt) {
            const int cl = wn + nt * 8 + 2 * tig;    // cols cl, cl+1
            const float bx = Bb[cl], by = Bb[cl + 1];
            float v00 = acc[mt][nt][0] + bx, v01 = acc[mt][nt][1] + by;
            float v10 = acc[mt][nt][2] + bx, v11 = acc[mt][nt][3] + by;
            size_t base0 = ((size_t)(e * CAP + m0 + r0)) * (size_t)N + n0 + cl;
            if (FC1) {
                v00 = gelu_tanh(v00); v01 = gelu_tanh(v01);
                v10 = gelu_tanh(v10); v11 = gelu_tanh(v11);
                *(__half2*)(g_hidh + base0)                 = __floats2half2_rn(v00, v01);
                *(__half2*)(g_hidh + base0 + (size_t)8 * N) = __floats2half2_rn(v10, v11);
            } else {
                *(float2*)(out + base0)                 = make_float2(v00, v01);
                *(float2*)(out + base0 + (size_t)8 * N) = make_float2(v10, v11);
            }
        }
    }
}

// ---------------- launch ----------------
extern "C" void kernel_launch(void* const* d_in, const int* in_sizes, int n_in,
                              void* d_out, int out_size)
{
    const float* x  = (const float*)d_in[0];
    // d_in[1] = tokens_per_expert (equal capacity; unused)
    const float* w1 = (const float*)d_in[2];
    const float* b1 = (const float*)d_in[3];
    const float* w2 = (const float*)d_in[4];
    const float* b2 = (const float*)d_in[5];
    float* out = (float*)d_out;

    cudaFuncSetAttribute(moe_gemm<true>,
                         cudaFuncAttributeMaxDynamicSharedMemorySize, SMEM_SIZE);
    cudaFuncSetAttribute(moe_gemm<false>,
                         cudaFuncAttributeMaxDynamicSharedMemorySize, SMEM_SIZE);

    __half* xh;  cudaGetSymbolAddress((void**)&xh,  g_xh);
    __half* w1h; cudaGetSymbolAddress((void**)&w1h, g_w1h);
    __half* w2h; cudaGetSymbolAddress((void**)&w2h, g_w2h);

    // 1) fp32 -> fp16 staging (RN)
    cvt_f2h<<<2048, 256>>>(x,  xh,  (size_t)TOKENS  * HDIM / 4);
    cvt_f2h<<<4096, 256>>>(w1, w1h, (size_t)EXPERTS * HDIM * FDIM / 4);
    cvt_f2h<<<4096, 256>>>(w2, w2h, (size_t)EXPERTS * FDIM * HDIM / 4);

    // 2) fc1 + GELU -> g_hidh (fp16)
    moe_gemm<true><<<dim3(FDIM / 128, CAP / 128, EXPERTS), 256, SMEM_SIZE>>>(
        b1, nullptr, HDIM, FDIM);
    // 3) fc2 -> out (fp32)
    moe_gemm<false><<<dim3(HDIM / 128, CAP / 128, EXPERTS), 256, SMEM_SIZE>>>(
        b2, out, FDIM, HDIM);
}

// round 7
// speedup vs baseline: 1.2706x; 1.2706x over previous
#include <cuda_runtime.h>
#include <cuda_fp16.h>
#include <cstdint>
#include <cstddef>

// ---------------- problem constants ----------------
#define EXPERTS 8
#define HDIM    2048
#define FDIM    8192
#define TOKENS  16384
#define CAP     2048

// fp16 staging buffers (static __device__ memory: allocation-guard safe)
__device__ __half g_xh [(size_t)TOKENS  * HDIM];          //  64 MB
__device__ __half g_w1h[(size_t)EXPERTS * HDIM * FDIM];   // 256 MB
__device__ __half g_w2h[(size_t)EXPERTS * FDIM * HDIM];   // 256 MB
__device__ __half g_hidh[(size_t)TOKENS * FDIM];          // 256 MB

// ---------------- fp32 -> fp16 (RN) bulk convert ----------------
__global__ void cvt_f2h(const float* __restrict__ s, __half* __restrict__ d, size_t n4) {
    size_t i      = blockIdx.x * (size_t)blockDim.x + threadIdx.x;
    size_t stride = (size_t)gridDim.x * blockDim.x;
    const float4* s4 = (const float4*)s;
    __half2*      d2 = (__half2*)d;
    for (; i < n4; i += stride) {
        float4 v = s4[i];
        d2[2 * i]     = __floats2half2_rn(v.x, v.y);
        d2[2 * i + 1] = __floats2half2_rn(v.z, v.w);
    }
}

// ---------------- PTX helpers ----------------
__device__ __forceinline__ uint32_t smem_u32(const void* p) {
    uint32_t a;
    asm("{ .reg .u64 t; cvta.to.shared.u64 t, %1; cvt.u32.u64 %0, t; }" : "=r"(a) : "l"(p));
    return a;
}
__device__ __forceinline__ void cpa16(uint32_t dst, const void* src) {
    asm volatile("cp.async.cg.shared.global [%0], [%1], 16;" :: "r"(dst), "l"(src));
}
#define CP_COMMIT() asm volatile("cp.async.commit_group;" ::: "memory")
#define CP_WAIT3()  asm volatile("cp.async.wait_group 3;"  ::: "memory")

__device__ __forceinline__ void ldsm_x4(uint32_t* r, uint32_t a) {
    asm volatile("ldmatrix.sync.aligned.m8n8.x4.shared.b16 {%0,%1,%2,%3}, [%4];"
                 : "=r"(r[0]), "=r"(r[1]), "=r"(r[2]), "=r"(r[3]) : "r"(a));
}
__device__ __forceinline__ void ldsm_x4t(uint32_t* r, uint32_t a) {
    asm volatile("ldmatrix.sync.aligned.m8n8.x4.trans.shared.b16 {%0,%1,%2,%3}, [%4];"
                 : "=r"(r[0]), "=r"(r[1]), "=r"(r[2]), "=r"(r[3]) : "r"(a));
}
__device__ __forceinline__ void mma16816(float* c, const uint32_t* a, const uint32_t* b) {
    asm volatile(
        "mma.sync.aligned.m16n8k16.row.col.f32.f16.f16.f32 "
        "{%0,%1,%2,%3}, {%4,%5,%6,%7}, {%8,%9}, {%0,%1,%2,%3};"
        : "+f"(c[0]), "+f"(c[1]), "+f"(c[2]), "+f"(c[3])
        : "r"(a[0]), "r"(a[1]), "r"(a[2]), "r"(a[3]), "r"(b[0]), "r"(b[1]));
}

__device__ __forceinline__ float gelu_tanh(float x) {
    float x3 = x * x * x;
    float t  = tanhf(0.7978845608028654f * (x + 0.044715f * x3));
    return 0.5f * x * (1.0f + t);
}

// ---------------- SMEM layout ----------------
// BM=128, BN=128, BK=32, 5-stage ring (early prefetch distance 3) — R5 pipeline.
// A stage: 128 rows x 64B padded to 80B pitch  (5 x 16B, gcd(5,8)=1)  -> 10240 B
// B stage:  32 k-rows x 256B padded to 272B   (17 x 16B, gcd(17,8)=1) ->  8704 B
// 5 stages: 94720 B -> 2 CTAs/SM.
static constexpr int A_PITCH   = 80;
static constexpr int B_PITCH   = 272;
static constexpr int A_STAGE   = 128 * A_PITCH;         // 10240
static constexpr int B_STAGE   = 32 * B_PITCH;          //  8704
static constexpr int NSTAGE    = 5;
static constexpr int B_OFF     = NSTAGE * A_STAGE;      // 51200
static constexpr int SMEM_SIZE = B_OFF + NSTAGE * B_STAGE;  // 94720

// ---------------- grouped GEMM: OUT[e] = act(A[e] @ W[e] + bias[e]) ----------------
// CTA 128x128 with 128 threads: 4 warps in 2x2, warp tile 64x64.
// Per k16-step per warp: 4 A-LDSM + 4 B-LDSM feed 32 HMMA (4:1 vs 2.7:1 before),
// and two co-resident CTAs/SM give independent barrier domains for latency hiding.
template <bool FC1>
__global__ void __launch_bounds__(128, 2)
moe_gemm(const float* __restrict__ bias, float* __restrict__ out, int K, int N)
{
    extern __shared__ char smem[];
    const uint32_t sb = smem_u32(smem);
    const int tid  = threadIdx.x;
    const int wid  = tid >> 5;
    const int lane = tid & 31;

    const int e  = blockIdx.z;
    const int m0 = blockIdx.y * 128;
    const int n0 = blockIdx.x * 128;

    const __half* A = (FC1 ? g_xh  : g_hidh) + ((size_t)(e * CAP + m0)) * (size_t)K;
    const __half* W = (FC1 ? g_w1h : g_w2h) + (size_t)e * K * N + n0;

    const int wm = (wid & 1) * 64;   // warp row offset
    const int wn = (wid >> 1) * 64;  // warp col offset

    // producer mapping (128 threads): A tile 512 segs (4/row), B tile 512 segs
    // (16/row); 4 each per thread.
    auto load_stage = [&](int stage, int kc) {
        uint32_t aS = sb + stage * A_STAGE;
        uint32_t bS = sb + B_OFF + stage * B_STAGE;
        #pragma unroll
        for (int j = 0; j < 4; ++j) {
            const int idx = tid + 128 * j;
            const int row = idx >> 2, seg = idx & 3;
            cpa16(aS + row * A_PITCH + seg * 16,
                  A + (size_t)row * K + kc + seg * 8);
        }
        #pragma unroll
        for (int j = 0; j < 4; ++j) {
            const int idx = tid + 128 * j;
            const int r = idx >> 4, seg = idx & 15;
            cpa16(bS + r * B_PITCH + seg * 16,
                  W + (size_t)(kc + r) * N + seg * 8);
        }
    };

    const int nk = K / 32;
    load_stage(0, 0);  CP_COMMIT();
    load_stage(1, 32); CP_COMMIT();
    load_stage(2, 64); CP_COMMIT();

    float acc[4][8][4];
    #pragma unroll
    for (int i = 0; i < 4; ++i)
        #pragma unroll
        for (int j = 0; j < 8; ++j)
            #pragma unroll
            for (int q = 0; q < 4; ++q) acc[i][j][q] = 0.f;

    const int gid = lane >> 2, tig = lane & 3;
    // A ldmatrix (x4, non-trans)
    const uint32_t a_row  = lane & 15;
    const uint32_t a_koff = (lane >> 4) * 16;
    // B ldmatrix (x4, trans): mats 0,1 -> k 0-7/8-15; mats 2,3 -> +8 cols
    const int bmat  = lane >> 3;
    const int bt_k  = (bmat & 1) * 8 + (lane & 7);
    const int bt_n  = (bmat >> 1) * 8;

    for (int it = 0; it < nk; ++it) {
        // Early prefetch (distance 3): slot (it+3)%5 was last consumed at it-2,
        // already guarded by the previous barrier; LDG latency overlaps the sync.
        const int pre = it + 3;
        if (pre < nk) { load_stage(pre % NSTAGE, pre * 32); CP_COMMIT(); }

        CP_WAIT3();               // <=3 groups pending -> stage `it` complete
        __syncthreads();

        const int s = it % NSTAGE;
        const uint32_t aS = sb + s * A_STAGE;
        const uint32_t bS = sb + B_OFF + s * B_STAGE;

        #pragma unroll
        for (int ks = 0; ks < 2; ++ks) {             // two k=16 steps per BK=32
            uint32_t a[4][4], b[4][4];
            #pragma unroll
            for (int mt = 0; mt < 4; ++mt)
                ldsm_x4(a[mt], aS + (wm + mt * 16 + a_row) * A_PITCH + ks * 32 + a_koff);
            #pragma unroll
            for (int nh = 0; nh < 4; ++nh)            // each yields two n8 blocks
                ldsm_x4t(b[nh], bS + (ks * 16 + bt_k) * B_PITCH + (wn + nh * 16 + bt_n) * 2);
            #pragma unroll
            for (int mt = 0; mt < 4; ++mt)
                #pragma unroll
                for (int nt = 0; nt < 8; ++nt)
                    mma16816(acc[mt][nt], a[mt], &b[nt >> 1][(nt & 1) * 2]);
        }
    }

    // ---------------- epilogue ----------------
    const float* Bb = bias + (size_t)e * N + n0;
    #pragma unroll
    for (int mt = 0; mt < 4; ++mt) {
        const int r0 = wm + mt * 16 + gid;           // rows r0 and r0+8
        #pragma unroll
        for (int nt = 0; nt < 8; ++nt) {
            const int cl = wn + nt * 8 + 2 * tig;    // cols cl, cl+1
            const float bx = Bb[cl], by = Bb[cl + 1];
            float v00 = acc[mt][nt][0] + bx, v01 = acc[mt][nt][1] + by;
            float v10 = acc[mt][nt][2] + bx, v11 = acc[mt][nt][3] + by;
            size_t base0 = ((size_t)(e * CAP + m0 + r0)) * (size_t)N + n0 + cl;
            if (FC1) {
                v00 = gelu_tanh(v00); v01 = gelu_tanh(v01);
                v10 = gelu_tanh(v10); v11 = gelu_tanh(v11);
                *(__half2*)(g_hidh + base0)                 = __floats2half2_rn(v00, v01);
                *(__half2*)(g_hidh + base0 + (size_t)8 * N) = __floats2half2_rn(v10, v11);
            } else {
                *(float2*)(out + base0)                 = make_float2(v00, v01);
                *(float2*)(out + base0 + (size_t)8 * N) = make_float2(v10, v11);
            }
        }
    }
}

// ---------------- launch ----------------
extern "C" void kernel_launch(void* const* d_in, const int* in_sizes, int n_in,
                              void* d_out, int out_size)
{
    const float* x  = (const float*)d_in[0];
    // d_in[1] = tokens_per_expert (equal capacity; unused)
    const float* w1 = (const float*)d_in[2];
    const float* b1 = (const float*)d_in[3];
    const float* w2 = (const float*)d_in[4];
    const float* b2 = (const float*)d_in[5];
    float* out = (float*)d_out;

    cudaFuncSetAttribute(moe_gemm<true>,
                         cudaFuncAttributeMaxDynamicSharedMemorySize, SMEM_SIZE);
    cudaFuncSetAttribute(moe_gemm<false>,
                         cudaFuncAttributeMaxDynamicSharedMemorySize, SMEM_SIZE);

    __half* xh;  cudaGetSymbolAddress((void**)&xh,  g_xh);
    __half* w1h; cudaGetSymbolAddress((void**)&w1h, g_w1h);
    __half* w2h; cudaGetSymbolAddress((void**)&w2h, g_w2h);

    // 1) fp32 -> fp16 staging (RN)
    cvt_f2h<<<2048, 256>>>(x,  xh,  (size_t)TOKENS  * HDIM / 4);
    cvt_f2h<<<4096, 256>>>(w1, w1h, (size_t)EXPERTS * HDIM * FDIM / 4);
    cvt_f2h<<<4096, 256>>>(w2, w2h, (size_t)EXPERTS * FDIM * HDIM / 4);

    // 2) fc1 + GELU -> g_hidh (fp16)
    moe_gemm<true><<<dim3(FDIM / 128, CAP / 128, EXPERTS), 128, SMEM_SIZE>>>(
        b1, nullptr, HDIM, FDIM);
    // 3) fc2 -> out (fp32)
    moe_gemm<false><<<dim3(HDIM / 128, CAP / 128, EXPERTS), 128, SMEM_SIZE>>>(
        b2, out, FDIM, HDIM);
}